// round 2
// baseline (speedup 1.0000x reference)
#include <cuda_runtime.h>

// LbpBlock: out = concat([x, pad(x_cat)], ch axis)
//   y[n,o,h,w] = sum_c x[n,c,h,w]*conv_w[o,c]   (c=3, o=64)
//   x_cat interior = sum_l H(y_c - y_shift_l) * exp(w[o,l]), zero border.
// x: (8,3,256,256) f32, conv_w: (64,3), w: (64,8) -> out: (8,67,256,256)

#define NN   8
#define CIN  3
#define OCH  64
#define HH   256
#define WW   256
#define TH   16
#define TW   128
#define OC   4
#define NCHUNK (OCH / OC)        // 16
#define HALO_H (TH + 2)          // 18
#define HALO_W (TW + 2)          // 130
#define HALO_N (HALO_H * HALO_W) // 2340
#define CP   146                 // swizzled float4 row pitch (sw(129)=145)

__device__ __forceinline__ int sw(int c) { return c + (c >> 3); }

__global__ __launch_bounds__(256, 2)
void lbp_main(const float* __restrict__ x,
              const float* __restrict__ cw,
              const float* __restrict__ w,
              float* __restrict__ out)
{
    __shared__ float4 sy[HALO_H][CP];   // y (4 channels packed) for current chunk
    __shared__ float  sew[OCH][8];      // exp(w)
    __shared__ float4 scw4[OCH];        // conv_w rows (padded)

    const int tid = threadIdx.x;
    const int n   = blockIdx.z;
    const int h0  = blockIdx.y * TH;
    const int w0  = blockIdx.x * TW;

    for (int i = tid; i < OCH * 8; i += 256)
        sew[i >> 3][i & 7] = __expf(w[i]);
    for (int i = tid; i < OCH; i += 256)
        scw4[i] = make_float4(cw[3 * i], cw[3 * i + 1], cw[3 * i + 2], 0.f);
    __syncthreads();

    const int mc   = tid & 31;      // col group (4 px)
    const int mrg  = tid >> 5;      // row group (2 rows)
    const int tr0  = mrg * 2;       // tile row of first pixel row
    const int oh0  = h0 + tr0;
    const int owbase = w0 + mc * 4;
    const int sc0  = mc * 4;        // halo col base (reads cols sc0..sc0+5)

    const float* xn = x + n * (CIN * HH * WW);

    for (int ch = 0; ch < NCHUNK; ch++) {
        const int o0 = ch * OC;

        // ---- phase 1: y halo for this 4-channel chunk (x from L2) ----
        {
            const float4 cw0 = scw4[o0], cw1 = scw4[o0 + 1];
            const float4 cw2 = scw4[o0 + 2], cw3 = scw4[o0 + 3];
            #pragma unroll
            for (int k = 0; k < 10; k++) {
                const int p = tid + k * 256;
                if (p < HALO_N) {
                    const int r = p / HALO_W;
                    const int c = p - r * HALO_W;
                    const int gh = h0 - 1 + r;
                    const int gw = w0 - 1 + c;
                    float x0 = 0.f, x1 = 0.f, x2 = 0.f;
                    if ((unsigned)gh < HH && (unsigned)gw < WW) {
                        const int base = gh * WW + gw;
                        x0 = xn[base];
                        x1 = xn[base + HH * WW];
                        x2 = xn[base + 2 * HH * WW];
                    }
                    float4 v;
                    v.x = fmaf(x2, cw0.z, fmaf(x1, cw0.y, x0 * cw0.x));
                    v.y = fmaf(x2, cw1.z, fmaf(x1, cw1.y, x0 * cw1.x));
                    v.z = fmaf(x2, cw2.z, fmaf(x1, cw2.y, x0 * cw2.x));
                    v.w = fmaf(x2, cw3.z, fmaf(x1, cw3.y, x0 * cw3.x));
                    sy[r][sw(c)] = v;
                }
            }
        }
        __syncthreads();

        // ---- phase 2: LBP, 2 rows x 4 cols per thread, rolling window ----
        float ew[OC][8];
        #pragma unroll
        for (int oc = 0; oc < OC; oc++)
            #pragma unroll
            for (int l = 0; l < 8; l++)
                ew[oc][l] = sew[o0 + oc][l];

        float4 t0[6], t1[6], t2[6];
        #pragma unroll
        for (int c = 0; c < 6; c++) {
            t0[c] = sy[tr0    ][sw(sc0 + c)];
            t1[c] = sy[tr0 + 1][sw(sc0 + c)];
            t2[c] = sy[tr0 + 2][sw(sc0 + c)];
        }

        const int obase = (n * 67 + 3 + o0) * HH * WW;

        #pragma unroll
        for (int pr = 0; pr < 2; pr++) {
            if (pr == 1) {
                #pragma unroll
                for (int c = 0; c < 6; c++) {
                    t0[c] = t1[c];
                    t1[c] = t2[c];
                    t2[c] = sy[tr0 + 3][sw(sc0 + c)];
                }
            }
            const int oh = oh0 + pr;
            const bool hv = ((unsigned)(oh - 1) < (unsigned)(HH - 2));

            float r0[4], r1[4], r2[4], r3[4];
            #pragma unroll
            for (int jj = 0; jj < 4; jj++) {
                const float4 ce = t1[jj + 1];
                float a0 = 0.f, a1 = 0.f, a2 = 0.f, a3 = 0.f;

                #define ACC(S, L) { const float4 s_ = (S);       \
                    if (ce.x > s_.x) a0 += ew[0][L];             \
                    if (ce.y > s_.y) a1 += ew[1][L];             \
                    if (ce.z > s_.z) a2 += ew[2][L];             \
                    if (ce.w > s_.w) a3 += ew[3][L]; }

                // TL, T, TR, L, BL, B, BR, R (reference shift order)
                ACC(t0[jj    ], 0)
                ACC(t0[jj + 1], 1)
                ACC(t0[jj + 2], 2)
                ACC(t1[jj    ], 3)
                ACC(t2[jj    ], 4)
                ACC(t2[jj + 1], 5)
                ACC(t2[jj + 2], 6)
                ACC(t1[jj + 2], 7)
                #undef ACC

                const int ow = owbase + jj;
                const bool v = hv && ((unsigned)(ow - 1) < (unsigned)(WW - 2));
                r0[jj] = v ? a0 : 0.f;
                r1[jj] = v ? a1 : 0.f;
                r2[jj] = v ? a2 : 0.f;
                r3[jj] = v ? a3 : 0.f;
            }

            const int ob = obase + oh * WW + owbase;
            *(float4*)(out + ob              ) = make_float4(r0[0], r0[1], r0[2], r0[3]);
            *(float4*)(out + ob +     HH * WW) = make_float4(r1[0], r1[1], r1[2], r1[3]);
            *(float4*)(out + ob + 2 * HH * WW) = make_float4(r2[0], r2[1], r2[2], r2[3]);
            *(float4*)(out + ob + 3 * HH * WW) = make_float4(r3[0], r3[1], r3[2], r3[3]);
        }
        __syncthreads();   // sy reused next chunk
    }
}

// copy x -> out channels [0,3)
__global__ __launch_bounds__(256)
void copy_x(const float4* __restrict__ x4, float4* __restrict__ out4)
{
    const int i = blockIdx.x * 256 + threadIdx.x;
    const int plane4 = HH * WW / 4;
    if (i >= NN * CIN * plane4) return;
    const int nc  = i / plane4;
    const int rem = i - nc * plane4;
    const int n = nc / CIN, c = nc - n * CIN;
    out4[(n * 67 + c) * plane4 + rem] = x4[i];
}

extern "C" void kernel_launch(void* const* d_in, const int* in_sizes, int n_in,
                              void* d_out, int out_size)
{
    const float* x  = (const float*)d_in[0];
    const float* cw = (const float*)d_in[1];
    const float* w  = (const float*)d_in[2];
    float* out = (float*)d_out;

    copy_x<<<(NN * CIN * HH * WW / 4 + 255) / 256, 256>>>(
        (const float4*)x, (float4*)out);

    dim3 grid(WW / TW, HH / TH, NN);   // (2, 16, 8) = 256 blocks
    lbp_main<<<grid, 256>>>(x, cw, w, out);
}

// round 3
// speedup vs baseline: 1.4172x; 1.4172x over previous
#include <cuda_runtime.h>

// LbpBlock: out = concat([x, pad(x_cat)], ch axis)
//   y[n,o,h,w] = sum_c x[n,c,h,w]*conv_w[o,c]   (c=3, o=64)
//   x_cat interior = sum_l H(y_c - y_shift_l) * exp(w[o,l]), zero border.
// x: (8,3,256,256) f32, conv_w: (64,3), w: (64,8) -> out: (8,67,256,256)

#define NN   8
#define CIN  3
#define OCH  64
#define HH   256
#define WW   256
#define TH   16
#define TW   64
#define OC   4
#define NCHUNK (OCH / OC)        // 16
#define HALO_H (TH + 2)          // 18
#define HALO_W (TW + 2)          // 66
#define HALO_N (HALO_H * HALO_W) // 1188
#define CP   74                  // swizzled float4 row pitch (sw(65)=73)
#define PLANE (HH * WW)

__device__ __forceinline__ int sw(int c) { return c + (c >> 3); }

__global__ __launch_bounds__(256, 2)
void lbp_main(const float* __restrict__ x,
              const float* __restrict__ cw,
              const float* __restrict__ w,
              float* __restrict__ out)
{
    __shared__ float4 sy[2][HALO_H][CP];   // double-buffered y (4ch packed)
    __shared__ float  sew[OCH][8];         // exp(w)
    __shared__ float4 scw4[OCH];           // conv_w rows

    const int tid = threadIdx.x;
    const int n   = blockIdx.z;
    const int h0  = blockIdx.y * TH;
    const int w0  = blockIdx.x * TW;

    for (int i = tid; i < OCH * 8; i += 256)
        sew[i >> 3][i & 7] = __expf(w[i]);
    for (int i = tid; i < OCH; i += 256)
        scw4[i] = make_float4(cw[3 * i], cw[3 * i + 1], cw[3 * i + 2], 0.f);

    // ---- x halo cached in registers (5 px / thread) ----
    float xr[5][3];
    int   syoff[5];
    #pragma unroll
    for (int k = 0; k < 5; k++) {
        const int p = tid + k * 256;
        const int r = p / HALO_W;
        const int c = p - r * HALO_W;
        syoff[k] = r * CP + sw(c);
        float v0 = 0.f, v1 = 0.f, v2 = 0.f;
        if (p < HALO_N) {
            const int gh = h0 - 1 + r;
            const int gw = w0 - 1 + c;
            if ((unsigned)gh < HH && (unsigned)gw < WW) {
                const int base = (n * CIN * HH + gh) * WW + gw;
                v0 = x[base];
                v1 = x[base + PLANE];
                v2 = x[base + 2 * PLANE];
            }
        }
        xr[k][0] = v0; xr[k][1] = v1; xr[k][2] = v2;
    }

    // ---- fused copy: x -> out channels [0,3) for this tile ----
    {
        const float4* xs = (const float4*)(x + n * CIN * PLANE);
        float4*       od = (float4*)(out + n * 67 * PLANE);
        #pragma unroll
        for (int k = 0; k < 3; k++) {
            const int f  = tid + k * 256;               // 768 float4 per tile
            const int c  = f >> 8;                      // channel
            const int rr = (f & 255) >> 4;              // row in tile
            const int cc = f & 15;                      // float4 col in tile
            const int idx = c * (PLANE / 4) + (h0 + rr) * (WW / 4) + (w0 / 4) + cc;
            od[idx] = xs[idx];
        }
    }
    __syncthreads();   // scw4 visible

    // ---- phase 1 for chunk 0 into buffer 0 ----
    {
        const float4 c0 = scw4[0], c1 = scw4[1], c2 = scw4[2], c3 = scw4[3];
        #pragma unroll
        for (int k = 0; k < 5; k++) {
            if (tid + k * 256 < HALO_N) {
                const float x0 = xr[k][0], x1 = xr[k][1], x2 = xr[k][2];
                float4 v;
                v.x = fmaf(x2, c0.z, fmaf(x1, c0.y, x0 * c0.x));
                v.y = fmaf(x2, c1.z, fmaf(x1, c1.y, x0 * c1.x));
                v.z = fmaf(x2, c2.z, fmaf(x1, c2.y, x0 * c2.x));
                v.w = fmaf(x2, c3.z, fmaf(x1, c3.y, x0 * c3.x));
                ((float4*)sy[0])[syoff[k]] = v;
            }
        }
    }
    __syncthreads();

    const int mc   = tid & 15;          // col group (4 px)
    const int mr   = tid >> 4;          // row in tile
    const int oh   = h0 + mr;
    const int owbase = w0 + mc * 4;
    const int sc0  = mc * 4;            // halo col of left neighbor of px0
    const bool hv  = ((unsigned)(oh - 1) < (unsigned)(HH - 2));

    for (int ch = 0; ch < NCHUNK; ch++) {
        const int o0 = ch * OC;
        float4 (*cur)[CP] = sy[ch & 1];
        float4 (*nxt)[CP] = sy[(ch & 1) ^ 1];

        // ---- window batch 1: halo columns sc0..sc0+3, 3 rows ----
        float4 c0a[3], c1a[3], c2a[3], c3a[3];
        #pragma unroll
        for (int r = 0; r < 3; r++) {
            c0a[r] = cur[mr + r][sw(sc0 + 0)];
            c1a[r] = cur[mr + r][sw(sc0 + 1)];
            c2a[r] = cur[mr + r][sw(sc0 + 2)];
            c3a[r] = cur[mr + r][sw(sc0 + 3)];
        }

        // ---- phase 1 for next chunk (reg FMA + STS; hides LDS latency) ----
        if (ch + 1 < NCHUNK) {
            const int q0 = (ch + 1) * OC;
            const float4 w0r = scw4[q0], w1r = scw4[q0 + 1];
            const float4 w2r = scw4[q0 + 2], w3r = scw4[q0 + 3];
            #pragma unroll
            for (int k = 0; k < 5; k++) {
                if (tid + k * 256 < HALO_N) {
                    const float x0 = xr[k][0], x1 = xr[k][1], x2 = xr[k][2];
                    float4 v;
                    v.x = fmaf(x2, w0r.z, fmaf(x1, w0r.y, x0 * w0r.x));
                    v.y = fmaf(x2, w1r.z, fmaf(x1, w1r.y, x0 * w1r.x));
                    v.z = fmaf(x2, w2r.z, fmaf(x1, w2r.y, x0 * w2r.x));
                    v.w = fmaf(x2, w3r.z, fmaf(x1, w3r.y, x0 * w3r.x));
                    ((float4*)nxt)[syoff[k]] = v;
                }
            }
        }

        // ---- per-chunk exp weights ----
        float ew[OC][8];
        #pragma unroll
        for (int oc = 0; oc < OC; oc++) {
            const float4 e0 = *(const float4*)&sew[o0 + oc][0];
            const float4 e1 = *(const float4*)&sew[o0 + oc][4];
            ew[oc][0] = e0.x; ew[oc][1] = e0.y; ew[oc][2] = e0.z; ew[oc][3] = e0.w;
            ew[oc][4] = e1.x; ew[oc][5] = e1.y; ew[oc][6] = e1.z; ew[oc][7] = e1.w;
        }

        float res[OC][4];

        #define ACC(S, L) { const float4 s_ = (S);       \
            if (ce.x > s_.x) a0 += ew[0][L];             \
            if (ce.y > s_.y) a1 += ew[1][L];             \
            if (ce.z > s_.z) a2 += ew[2][L];             \
            if (ce.w > s_.w) a3 += ew[3][L]; }

        // PX: Wl/Wc/Wr are 3-row column arrays (halo cols jj, jj+1, jj+2)
        #define PX(jj, Wl, Wc, Wr) {                                        \
            const float4 ce = Wc[1];                                        \
            float a0 = 0.f, a1 = 0.f, a2 = 0.f, a3 = 0.f;                   \
            ACC(Wl[0], 0) ACC(Wc[0], 1) ACC(Wr[0], 2)                       \
            ACC(Wl[1], 3) ACC(Wl[2], 4) ACC(Wc[2], 5)                       \
            ACC(Wr[2], 6) ACC(Wr[1], 7)                                     \
            const int ow = owbase + jj;                                     \
            const bool v = hv && ((unsigned)(ow - 1) < (unsigned)(WW - 2)); \
            res[0][jj] = v ? a0 : 0.f;                                      \
            res[1][jj] = v ? a1 : 0.f;                                      \
            res[2][jj] = v ? a2 : 0.f;                                      \
            res[3][jj] = v ? a3 : 0.f;                                      \
        }

        PX(0, c0a, c1a, c2a)
        PX(1, c1a, c2a, c3a)

        // ---- window batch 2: halo columns sc0+4, sc0+5 (c0a/c1a dead) ----
        float4 c4a[3], c5a[3];
        #pragma unroll
        for (int r = 0; r < 3; r++) {
            c4a[r] = cur[mr + r][sw(sc0 + 4)];
            c5a[r] = cur[mr + r][sw(sc0 + 5)];
        }

        PX(2, c2a, c3a, c4a)
        PX(3, c3a, c4a, c5a)
        #undef PX
        #undef ACC

        // ---- coalesced float4 stores ----
        const int ob = ((n * 67 + 3 + o0) * HH + oh) * WW + owbase;
        *(float4*)(out + ob            ) = make_float4(res[0][0], res[0][1], res[0][2], res[0][3]);
        *(float4*)(out + ob +     PLANE) = make_float4(res[1][0], res[1][1], res[1][2], res[1][3]);
        *(float4*)(out + ob + 2 * PLANE) = make_float4(res[2][0], res[2][1], res[2][2], res[2][3]);
        *(float4*)(out + ob + 3 * PLANE) = make_float4(res[3][0], res[3][1], res[3][2], res[3][3]);

        __syncthreads();   // nxt writes visible; cur free for next chunk
    }
}

extern "C" void kernel_launch(void* const* d_in, const int* in_sizes, int n_in,
                              void* d_out, int out_size)
{
    const float* x  = (const float*)d_in[0];
    const float* cw = (const float*)d_in[1];
    const float* w  = (const float*)d_in[2];
    float* out = (float*)d_out;

    dim3 grid(WW / TW, HH / TH, NN);   // (4, 16, 8) = 512 blocks
    lbp_main<<<grid, 256>>>(x, cw, w, out);
}